// round 16
// baseline (speedup 1.0000x reference)
#include <cuda_runtime.h>
#include <cuda_bf16.h>
#include <math.h>
#include <stdint.h>

#define B_   256
#define IN_  1024
#define D_   512
#define P_   2048
#define SPLITK 8
#define NT_P  (P_ / 64)     // 32 proxy n-tiles per row

// ---------------- scratch (device globals; no allocations allowed) ---------
__device__ float g_feat_part[SPLITK * B_ * D_];   // split-K partials for GEMM1
__device__ float g_featT[B_ * D_];                // tf32-rounded feat
__device__ float g_feat_n2[B_];                   // per-row ||feat||^2 (rounded feat)
__device__ float g_pmax[B_ * NT_P];               // per (row, n-tile) partial max
__device__ float g_psum[B_ * NT_P];               // per (row, n-tile) partial sumexp
__device__ float g_sy[B_];                        // s[b, y[b]]
__device__ int   g_grp[32];                       // per-(m0,n0) split-K counters
__device__ int   g_done;                          // proxy-CTA completion counter

// ==================== tf32 mma.sync helpers ================================
__device__ __forceinline__ void mma_tf32(float c[4], const uint32_t a[4], const uint32_t b[2]) {
    asm volatile("mma.sync.aligned.m16n8k8.row.col.f32.tf32.tf32.f32 "
        "{%0,%1,%2,%3}, {%4,%5,%6,%7}, {%8,%9}, {%0,%1,%2,%3};"
        : "+f"(c[0]), "+f"(c[1]), "+f"(c[2]), "+f"(c[3])
        : "r"(a[0]), "r"(a[1]), "r"(a[2]), "r"(a[3]), "r"(b[0]), "r"(b[1]));
}

__device__ __forceinline__ float to_tf32(float x) {
    uint32_t r;
    asm("cvt.rna.tf32.f32 %0, %1;" : "=r"(r) : "f"(x));
    return __uint_as_float(r);
}
__device__ __forceinline__ uint32_t fu(float x) { return __float_as_uint(x); }

// SMEM: plain row-major, row stride 36 words (144B). Fragment reads are
// conflict-free LDS.32; loader STS.128 phases are at the bandwidth floor.
#define RS_W 36

// One Kc=32 chunk of warp mma (warp tile (16*WM16) x (8*WN8)).
template<int WM16, int WN8>
__device__ __forceinline__ void chunk_mma(const float* __restrict__ As,
        const float* __restrict__ Bs, int wm, int wn, int g, int t,
        float acc[WM16][WN8][4])
{
#pragma unroll
    for (int j = 0; j < 4; j++) {
        uint32_t af[WM16][4];
#pragma unroll
        for (int i = 0; i < WM16; i++) {
            const float* base = As + (wm + i * 16 + g) * RS_W + j * 8 + t;
            af[i][0] = fu(base[0]);
            af[i][1] = fu(base[8 * RS_W]);
            af[i][2] = fu(base[4]);
            af[i][3] = fu(base[8 * RS_W + 4]);
        }
        uint32_t bf[WN8][2];
#pragma unroll
        for (int nn = 0; nn < WN8; nn++) {
            const float* base = Bs + (wn + nn * 8 + g) * RS_W + j * 8 + t;
            bf[nn][0] = fu(base[0]);
            bf[nn][1] = fu(base[4]);
        }
#pragma unroll
        for (int i = 0; i < WM16; i++)
#pragma unroll
            for (int nn = 0; nn < WN8; nn++)
                mma_tf32(acc[i][nn], af[i], bf[nn]);
    }
}

// ---------------- GEMM1: x @ Wb^T split-K(8) + fused last-slice combine ----
// 64x64 tile, 256 thr: warps 0-3 mma (32x32 tile), warps 4-7 loaders
// (32 rows each, contiguous LDG, 2-chunk-ahead prefetch). grid (8,4,8).
__global__ __launch_bounds__(256, 2)
void gemm1_mma(const float* __restrict__ x, const float* __restrict__ Wb,
               const float* __restrict__ bb)
{
    extern __shared__ __align__(16) float smem[];
    constexpr int TW = 64 * RS_W;               // 2304 words per segment
    constexpr int STG = 2 * TW;
    int* flag = (int*)(smem + 2 * STG);

    const int tid = threadIdx.x, wid = tid >> 5, lane = tid & 31;
    const int g = lane >> 2, t = lane & 3;
    const int n0 = blockIdx.x * 64, m0 = blockIdx.y * 64;
    const int z  = blockIdx.z;
    const int kb4 = z * ((IN_ / SPLITK) / 4);   // K-slice offset in float4 (32)
    const int wm = (wid & 1) * 32, wn = (wid >> 1) * 32;

    // loader mapping: lw 0,1 -> A rows 0/32; lw 2,3 -> B rows 0/32
    const int lw = wid - 4;
    const int sub = lane >> 3, u = lane & 7;
    const bool ldA = lw < 2;
    const int rbase = (lw & 1) * 32 + sub;      // + 4i, i<8
    const float4* rp4 = (const float4*)(ldA ? (x + (size_t)(m0 + rbase) * IN_)
                                            : (Wb + (size_t)(n0 + rbase) * IN_));
    const int wbase = (ldA ? 0 : TW) + rbase * RS_W + u * 4;

    float acc[2][4][4] = {};
    float4 v[2][8];

    auto ld = [&](int c, int buf) {
#pragma unroll
        for (int i = 0; i < 8; i++)
            v[buf][i] = rp4[(size_t)i * IN_ + kb4 + c * 8 + u];
    };
    auto st = [&](int c, int buf) {
        float* base = smem + (c & 1) * STG + wbase;
#pragma unroll
        for (int i = 0; i < 8; i++) {
            float4 a = v[buf][i];
            *(float4*)(base + i * 4 * RS_W) =
                make_float4(to_tf32(a.x), to_tf32(a.y), to_tf32(a.z), to_tf32(a.w));
        }
    };

    constexpr int NCH = (IN_ / SPLITK) / 32;    // 4
    if (wid >= 4) { ld(0, 0); st(0, 0); ld(1, 1); }
    __syncthreads();
    for (int c = 0; c < NCH; c++) {
        if (wid < 4) {
            const float* stg = smem + (c & 1) * STG;
            chunk_mma<2, 4>(stg, stg + TW, wm, wn, g, t, acc);
        } else {
            if (c + 2 < NCH) ld(c + 2, c & 1);
            if (c + 1 < NCH) st(c + 1, (c + 1) & 1);
        }
        if (c + 1 < NCH) __syncthreads();
    }

    // mma warps write this slice's partials
    if (wid < 4) {
        float* dst = g_feat_part + (size_t)z * B_ * D_;
#pragma unroll
        for (int i = 0; i < 2; i++) {
            int m = m0 + wm + i * 16 + g;
#pragma unroll
            for (int nn = 0; nn < 4; nn++) {
                int n = n0 + wn + nn * 8 + 2 * t;
                *(float2*)(dst + (size_t)m * D_ + n) =
                    make_float2(acc[i][nn][0], acc[i][nn][1]);
                *(float2*)(dst + (size_t)(m + 8) * D_ + n) =
                    make_float2(acc[i][nn][2], acc[i][nn][3]);
            }
        }
    }

    // ---- last slice of this (m0,n0) group combines + bias + round ----------
    const int gid = blockIdx.y * 8 + blockIdx.x;
    __threadfence();
    __syncthreads();
    if (tid == 0) *flag = (atomicAdd(&g_grp[gid], 1) == SPLITK - 1) ? 1 : 0;
    __syncthreads();
    if (*flag == 0) return;
    __threadfence();                            // acquire other slices' writes

    // flat combine: 4096 floats = 1024 float4, 4 per thread
#pragma unroll
    for (int k = 0; k < 4; k++) {
        int idx4 = k * 256 + tid;
        int r = idx4 >> 4, c4 = idx4 & 15;
        size_t off = ((size_t)(m0 + r) * D_ + n0) / 4 + c4;
        float4 s = ((const float4*)bb)[(n0 >> 2) + c4];
#pragma unroll
        for (int zz = 0; zz < SPLITK; zz++) {
            float4 p = ((const float4*)g_feat_part)[(size_t)zz * (B_ * D_ / 4) + off];
            s.x += p.x; s.y += p.y; s.z += p.z; s.w += p.w;
        }
        ((float4*)g_featT)[off] =
            make_float4(to_tf32(s.x), to_tf32(s.y), to_tf32(s.z), to_tf32(s.w));
    }
    __syncthreads();
    if (tid == 0) atomicExch(&g_grp[gid], 0);   // reset for graph replay
}

// ---------------- fused GEMM2 (out) + GEMM3 + last-CTA finalize ------------
// 64x64 tile, K=512. grid (64, 4) = 256 CTAs, 256 thr, 2 CTAs/SM.
// Warps 0-3 mma (32x32), warps 4-7 loaders (2-chunk-ahead prefetch).
__global__ __launch_bounds__(256, 2)
void gemm23_mma(const float* __restrict__ Wm, const float* __restrict__ bm,
                const float* __restrict__ proxies, const int* __restrict__ y,
                float* __restrict__ out)
{
    extern __shared__ __align__(16) float smem[];
    constexpr int TAW = 64 * RS_W;              // 2304 words
    constexpr int STG = 2 * TAW;
    float* pn2s = smem + 2 * STG;               // [64]
    float* fn2s = pn2s + 64;                    // [64]
    float* pmx  = fn2s + 64;                    // [64][2] (+finalize reuse 256)
    float* psm  = pmx + 256;                    // [64][2] (+finalize reuse 256)
    int*   flag = (int*)(psm + 256);

    const int tid = threadIdx.x, wid = tid >> 5, lane = tid & 31;
    const int g = lane >> 2, t = lane & 3;
    const int nt = blockIdx.x;                  // 0..63
    const bool isp = (nt >= 32);
    const int n0 = (nt & 31) * 64;
    const int m0 = blockIdx.y * 64;
    const float* Bmat = isp ? proxies : Wm;
    const int wm = (wid & 1) * 32, wn = (wid >> 1) * 32;

    const int lw = wid - 4;
    const int sub = lane >> 3, u = lane & 7;
    const bool ldA = lw < 2;
    const int rbase = (lw & 1) * 32 + sub;
    const float4* rp4 = (const float4*)(ldA ? (g_featT + (size_t)(m0 + rbase) * D_)
                                            : (Bmat + (size_t)(n0 + rbase) * D_));
    const int wbase = (ldA ? 0 : TAW) + rbase * RS_W + u * 4;

    float acc[2][4][4] = {};
    float4 v[2][8];
    float sq[8] = {};

    auto ld = [&](int c, int buf) {
#pragma unroll
        for (int i = 0; i < 8; i++)
            v[buf][i] = rp4[(size_t)i * D_ + c * 8 + u];
    };
    auto st = [&](int c, int buf) {
        float* base = smem + (c & 1) * STG + wbase;
#pragma unroll
        for (int i = 0; i < 8; i++) {
            float4 a = v[buf][i];
            sq[i] += a.x * a.x + a.y * a.y + a.z * a.z + a.w * a.w;
            if (ldA)     // featT already tf32-rounded
                *(float4*)(base + i * 4 * RS_W) = a;
            else
                *(float4*)(base + i * 4 * RS_W) =
                    make_float4(to_tf32(a.x), to_tf32(a.y), to_tf32(a.z), to_tf32(a.w));
        }
    };

    constexpr int NCH = D_ / 32;                // 16
    if (wid >= 4) { ld(0, 0); st(0, 0); ld(1, 1); }
    __syncthreads();
    for (int c = 0; c < NCH; c++) {
        if (wid < 4) {
            const float* stg = smem + (c & 1) * STG;
            chunk_mma<2, 4>(stg, stg + TAW, wm, wn, g, t, acc);
        } else {
            if (c + 2 < NCH) ld(c + 2, c & 1);
            if (c + 1 < NCH) st(c + 1, (c + 1) & 1);
        }
        if (c + 1 < NCH) __syncthreads();
    }

    // loader warps: per-row sumsq (rows rbase+4i), reduce over u lanes
    if (wid >= 4) {
#pragma unroll
        for (int i = 0; i < 8; i++) {
            float s = sq[i];
            s += __shfl_xor_sync(0xffffffffu, s, 1);
            s += __shfl_xor_sync(0xffffffffu, s, 2);
            s += __shfl_xor_sync(0xffffffffu, s, 4);
            if (u == 0) {
                int row = rbase + 4 * i;
                if (ldA) fn2s[row] = s;
                else     pn2s[row] = s;
            }
        }
    }
    __syncthreads();

    if (!isp) {
        if (wid < 4) {
#pragma unroll
            for (int i = 0; i < 2; i++) {
                int m = m0 + wm + i * 16 + g;
#pragma unroll
                for (int nn = 0; nn < 4; nn++) {
                    int n = n0 + wn + nn * 8 + 2 * t;
                    float bn0 = bm[n], bn1 = bm[n + 1];
                    *(float2*)(out + (size_t)m * P_ + n) =
                        make_float2(acc[i][nn][0] + bn0, acc[i][nn][1] + bn1);
                    *(float2*)(out + (size_t)(m + 8) * P_ + n) =
                        make_float2(acc[i][nn][2] + bn0, acc[i][nn][3] + bn1);
                }
            }
        }
        return;
    }

    // export fn2 for reg_e (4 CTAs with nt==32 cover all 256 rows)
    if (nt == 32 && tid < 64) g_feat_n2[m0 + tid] = fn2s[tid];

    // proxy: s = 2*dot - fn2 - pn2 in regs -> per-(row, wn-half) (max, sumexp)
    if (wid < 4) {
        const int half = wid >> 1;
#pragma unroll
        for (int i = 0; i < 2; i++) {
            const int rA = wm + i * 16 + g;
            const int rB = rA + 8;
            const float fa = fn2s[rA], fb = fn2s[rB];
            const int ya = y[m0 + rA], yb = y[m0 + rB];
            float sA[8], sB[8];
#pragma unroll
            for (int nn = 0; nn < 4; nn++) {
                int nl = wn + nn * 8 + 2 * t;
                float p0 = pn2s[nl], p1 = pn2s[nl + 1];
                sA[nn * 2 + 0] = 2.f * acc[i][nn][0] - fa - p0;
                sA[nn * 2 + 1] = 2.f * acc[i][nn][1] - fa - p1;
                sB[nn * 2 + 0] = 2.f * acc[i][nn][2] - fb - p0;
                sB[nn * 2 + 1] = 2.f * acc[i][nn][3] - fb - p1;
                int n = n0 + nl;
                if (n     == ya) g_sy[m0 + rA] = sA[nn * 2 + 0];
                if (n + 1 == ya) g_sy[m0 + rA] = sA[nn * 2 + 1];
                if (n     == yb) g_sy[m0 + rB] = sB[nn * 2 + 0];
                if (n + 1 == yb) g_sy[m0 + rB] = sB[nn * 2 + 1];
            }
            float mA = sA[0], mB = sB[0];
#pragma unroll
            for (int q = 1; q < 8; q++) { mA = fmaxf(mA, sA[q]); mB = fmaxf(mB, sB[q]); }
            float eA = 0.f, eB = 0.f;
#pragma unroll
            for (int q = 0; q < 8; q++) { eA += expf(sA[q] - mA); eB += expf(sB[q] - mB); }
#pragma unroll
            for (int o = 1; o <= 2; o <<= 1) {
                float mA2 = __shfl_xor_sync(0xffffffffu, mA, o);
                float eA2 = __shfl_xor_sync(0xffffffffu, eA, o);
                float mB2 = __shfl_xor_sync(0xffffffffu, mB, o);
                float eB2 = __shfl_xor_sync(0xffffffffu, eB, o);
                float M = fmaxf(mA, mA2);
                eA = eA * expf(mA - M) + eA2 * expf(mA2 - M); mA = M;
                M = fmaxf(mB, mB2);
                eB = eB * expf(mB - M) + eB2 * expf(mB2 - M); mB = M;
            }
            if (t == 0) {
                pmx[rA * 2 + half] = mA; psm[rA * 2 + half] = eA;
                pmx[rB * 2 + half] = mB; psm[rB * 2 + half] = eB;
            }
        }
    }
    __syncthreads();
    if (tid < 64) {
        float m1 = pmx[tid * 2], m2 = pmx[tid * 2 + 1];
        float M = fmaxf(m1, m2);
        float S = psm[tid * 2] * expf(m1 - M) + psm[tid * 2 + 1] * expf(m2 - M);
        int idx = (m0 + tid) * NT_P + (nt - 32);
        g_pmax[idx] = M;
        g_psum[idx] = S;
    }

    // ---- last-done proxy CTA finalizes loss + reg_e ------------------------
    __threadfence();
    __syncthreads();
    if (tid == 0) *flag = (atomicAdd(&g_done, 1) == 127) ? 1 : 0;
    __syncthreads();
    if (*flag == 0) return;
    __threadfence();

    float* r1 = pmx;                            // reuse smem [256]
    float* r2 = psm;                            // reuse smem [256]
    {
        const int b = tid;                      // one row per thread
        const float4* pm = (const float4*)(g_pmax + b * NT_P);
        const float4* ps = (const float4*)(g_psum + b * NT_P);
        float4 mv[8], sv[8];
#pragma unroll
        for (int q = 0; q < 8; q++) { mv[q] = pm[q]; sv[q] = ps[q]; }
        float M = -INFINITY;
#pragma unroll
        for (int q = 0; q < 8; q++)
            M = fmaxf(M, fmaxf(fmaxf(mv[q].x, mv[q].y), fmaxf(mv[q].z, mv[q].w)));
        float S = 0.f;
#pragma unroll
        for (int q = 0; q < 8; q++)
            S += sv[q].x * expf(mv[q].x - M) + sv[q].y * expf(mv[q].y - M)
               + sv[q].z * expf(mv[q].z - M) + sv[q].w * expf(mv[q].w - M);
        r1[b] = g_sy[b] - M - logf(S);          // logp[b, y[b]]
        r2[b] = sqrtf(g_feat_n2[b]);
    }
    __syncthreads();
    for (int stp = 128; stp > 0; stp >>= 1) {
        if (tid < stp) { r1[tid] += r1[tid + stp]; r2[tid] += r2[tid + stp]; }
        __syncthreads();
    }
    if (tid == 0) {
        out[(size_t)B_ * P_]     = -r1[0] / (float)B_;  // loss
        out[(size_t)B_ * P_ + 1] =  r2[0] / (float)B_;  // reg_e
        g_done = 0;                              // reset for graph replay
    }
}

// ---------------- launch ----------------------------------------------------
extern "C" void kernel_launch(void* const* d_in, const int* in_sizes, int n_in,
                              void* d_out, int out_size)
{
    const float* x       = (const float*)d_in[0];
    const int*   y       = (const int*)  d_in[1];
    const float* Wb      = (const float*)d_in[2];
    const float* bb      = (const float*)d_in[3];
    const float* Wm      = (const float*)d_in[4];
    const float* bm      = (const float*)d_in[5];
    const float* proxies = (const float*)d_in[6];
    float* out = (float*)d_out;

    const int SMEM1 = (4 * 64 * RS_W + 4) * 4;                        // ~36.9 KB
    const int SMEM2 = (4 * 64 * RS_W + 64 + 64 + 256 + 256 + 4) * 4;  // ~39.4 KB
    cudaFuncSetAttribute(gemm1_mma,  cudaFuncAttributeMaxDynamicSharedMemorySize, SMEM1);
    cudaFuncSetAttribute(gemm23_mma, cudaFuncAttributeMaxDynamicSharedMemorySize, SMEM2);

    // 1) feat: split-K(8) GEMM + fused last-slice combine (256 CTAs, 256 thr)
    gemm1_mma<<<dim3(D_ / 64, B_ / 64, SPLITK), 256, SMEM1>>>(x, Wb, bb);
    // 2) fused out-head + proxy softmax partials + last-CTA finalize
    //    (256 CTAs, 256 thr, 2 CTAs/SM)
    gemm23_mma<<<dim3(64, B_ / 64), 256, SMEM2>>>(Wm, bm, proxies, y, out);
}

// round 17
// speedup vs baseline: 1.1396x; 1.1396x over previous
#include <cuda_runtime.h>
#include <cuda_bf16.h>
#include <math.h>
#include <stdint.h>

#define B_   256
#define IN_  1024
#define D_   512
#define P_   2048
#define SPLITK 8
#define NT_P  (P_ / 64)     // 32 proxy n-tiles per row

// ---------------- scratch (device globals; no allocations allowed) ---------
__device__ float g_feat_part[SPLITK * B_ * D_];   // split-K partials for GEMM1
__device__ float g_featT[B_ * D_];                // tf32-rounded feat
__device__ float g_feat_n2[B_];                   // per-row ||feat||^2 (rounded feat)
__device__ float g_pmax[B_ * NT_P];               // per (row, n-tile) partial max
__device__ float g_psum[B_ * NT_P];               // per (row, n-tile) partial sumexp
__device__ float g_sy[B_];                        // s[b, y[b]]
__device__ int   g_grp[32];                       // per-(m0,n0) split-K counters
__device__ int   g_done;                          // proxy-CTA completion counter

// ==================== tf32 mma.sync helpers ================================
__device__ __forceinline__ void mma_tf32(float c[4], const uint32_t a[4], const uint32_t b[2]) {
    asm volatile("mma.sync.aligned.m16n8k8.row.col.f32.tf32.tf32.f32 "
        "{%0,%1,%2,%3}, {%4,%5,%6,%7}, {%8,%9}, {%0,%1,%2,%3};"
        : "+f"(c[0]), "+f"(c[1]), "+f"(c[2]), "+f"(c[3])
        : "r"(a[0]), "r"(a[1]), "r"(a[2]), "r"(a[3]), "r"(b[0]), "r"(b[1]));
}

__device__ __forceinline__ float to_tf32(float x) {
    uint32_t r;
    asm("cvt.rna.tf32.f32 %0, %1;" : "=r"(r) : "f"(x));
    return __uint_as_float(r);
}
__device__ __forceinline__ uint32_t fu(float x) { return __float_as_uint(x); }

// SMEM: plain row-major, row stride 36 words (144B). Fragment reads are
// conflict-free LDS.32; loader STS.128 phases are conflict-free.
#define RS_W 36

// One Kc=32 chunk of warp mma from row-major smem (LDS.32 fragments).
template<int WM16, int WN8>
__device__ __forceinline__ void chunk_mma(const float* __restrict__ As,
        const float* __restrict__ Bs, int wm, int wn, int g, int t,
        float acc[WM16][WN8][4])
{
#pragma unroll
    for (int j = 0; j < 4; j++) {
        uint32_t af[WM16][4];
#pragma unroll
        for (int i = 0; i < WM16; i++) {
            const float* base = As + (wm + i * 16 + g) * RS_W + j * 8 + t;
            af[i][0] = fu(base[0]);
            af[i][1] = fu(base[8 * RS_W]);
            af[i][2] = fu(base[4]);
            af[i][3] = fu(base[8 * RS_W + 4]);
        }
        uint32_t bf[WN8][2];
#pragma unroll
        for (int nn = 0; nn < WN8; nn++) {
            const float* base = Bs + (wn + nn * 8 + g) * RS_W + j * 8 + t;
            bf[nn][0] = fu(base[0]);
            bf[nn][1] = fu(base[4]);
        }
#pragma unroll
        for (int i = 0; i < WM16; i++)
#pragma unroll
            for (int nn = 0; nn < WN8; nn++)
                mma_tf32(acc[i][nn], af[i], bf[nn]);
    }
}

// ---------------- GEMM1: x @ Wb^T split-K(8) + fused last-slice combine ----
// 64x64 tile, K-slice 128 (4 chunks). grid (8,4,8) = 256 CTAs, 256 thr,
// 2 CTAs/SM. Fused loader+mma warps (R15-proven structure).
__global__ __launch_bounds__(256, 2)
void gemm1_mma(const float* __restrict__ x, const float* __restrict__ Wb,
               const float* __restrict__ bb)
{
    extern __shared__ __align__(16) float smem[];
    constexpr int TW = 64 * RS_W;               // 2304 words per segment
    constexpr int STG = 2 * TW;
    int* flag = (int*)(smem + 2 * STG);

    const int tid = threadIdx.x, wid = tid >> 5, lane = tid & 31;
    const int g = lane >> 2, t = lane & 3;
    const int n0 = blockIdx.x * 64, m0 = blockIdx.y * 64;
    const int z  = blockIdx.z;
    const int kb4 = z * ((IN_ / SPLITK) / 4);   // K-slice offset in float4 (32)
    const int wm = (wid & 1) * 32, wn = (wid >> 1) * 16;

    // loader mapping: 8 warps (A: 0-3, B: 4-7), 16 rows each; contiguous LDG
    const int sub = lane >> 3, u = lane & 7;
    const bool ldA = wid < 4;
    const int rbase = (ldA ? wid * 16 : (wid - 4) * 16) + sub;    // + 4i later
    const float4* rp4 = (const float4*)(ldA ? (x + (size_t)(m0 + rbase) * IN_)
                                            : (Wb + (size_t)(n0 + rbase) * IN_));
    const int wbase = (ldA ? 0 : TW) + rbase * RS_W + u * 4;

    float acc[2][2][4] = {};
    float4 v[4];

    auto ld = [&](int c) {
#pragma unroll
        for (int i = 0; i < 4; i++)
            v[i] = rp4[(size_t)i * IN_ + kb4 + c * 8 + u];
    };
    auto st = [&](int c) {
        float* base = smem + (c & 1) * STG + wbase;
#pragma unroll
        for (int i = 0; i < 4; i++) {
            float4 a = v[i];
            *(float4*)(base + i * 4 * RS_W) =
                make_float4(to_tf32(a.x), to_tf32(a.y), to_tf32(a.z), to_tf32(a.w));
        }
    };

    ld(0); st(0); __syncthreads();
    constexpr int NCH = (IN_ / SPLITK) / 32;    // 4
    for (int c = 0; c < NCH; c++) {
        if (c + 1 < NCH) ld(c + 1);
        const float* stg = smem + (c & 1) * STG;
        chunk_mma<2, 2>(stg, stg + TW, wm, wn, g, t, acc);
        if (c + 1 < NCH) { st(c + 1); __syncthreads(); }
    }

    // write this slice's partials
    {
        float* dst = g_feat_part + (size_t)z * B_ * D_;
#pragma unroll
        for (int i = 0; i < 2; i++) {
            int m = m0 + wm + i * 16 + g;
#pragma unroll
            for (int nn = 0; nn < 2; nn++) {
                int n = n0 + wn + nn * 8 + 2 * t;
                *(float2*)(dst + (size_t)m * D_ + n) =
                    make_float2(acc[i][nn][0], acc[i][nn][1]);
                *(float2*)(dst + (size_t)(m + 8) * D_ + n) =
                    make_float2(acc[i][nn][2], acc[i][nn][3]);
            }
        }
    }

    // ---- last slice of this (m0,n0) group combines + bias + round ----------
    const int gid = blockIdx.y * 8 + blockIdx.x;
    __threadfence();
    __syncthreads();
    if (tid == 0) *flag = (atomicAdd(&g_grp[gid], 1) == SPLITK - 1) ? 1 : 0;
    __syncthreads();
    if (*flag == 0) return;
    __threadfence();                            // acquire other slices' writes

    // flat combine: 64x64 tile = 1024 float4, 4 per thread
#pragma unroll
    for (int k = 0; k < 4; k++) {
        int idx4 = k * 256 + tid;
        int r = idx4 >> 4, c4 = idx4 & 15;
        size_t off = ((size_t)(m0 + r) * D_ + n0) / 4 + c4;
        float4 s = ((const float4*)bb)[(n0 >> 2) + c4];
#pragma unroll
        for (int zz = 0; zz < SPLITK; zz++) {
            float4 p = ((const float4*)g_feat_part)[(size_t)zz * (B_ * D_ / 4) + off];
            s.x += p.x; s.y += p.y; s.z += p.z; s.w += p.w;
        }
        ((float4*)g_featT)[off] =
            make_float4(to_tf32(s.x), to_tf32(s.y), to_tf32(s.z), to_tf32(s.w));
    }
    __syncthreads();
    if (tid == 0) atomicExch(&g_grp[gid], 0);   // reset for graph replay
}

// ---------------- fused GEMM2 (out) + GEMM3 + last-CTA finalize ------------
// Tile 64(m) x 64(n), K=512. grid (64, 4) = 256 CTAs, 256 thr, 2 CTAs/SM.
// (R15-proven version, unchanged)
__global__ __launch_bounds__(256, 2)
void gemm23_mma(const float* __restrict__ Wm, const float* __restrict__ bm,
                const float* __restrict__ proxies, const int* __restrict__ y,
                float* __restrict__ out)
{
    extern __shared__ __align__(16) float smem[];
    constexpr int TAW = 64 * RS_W;              // 2304 words
    constexpr int TBW = 64 * RS_W;              // 2304
    constexpr int STG = TAW + TBW;
    float* pn2s = smem + 2 * STG;               // [64]
    float* fn2s = pn2s + 64;                    // [64]
    float* pmx  = fn2s + 64;                    // [64][4]  (reused by finalize)
    float* psm  = pmx + 256;                    // [64][4]
    int*   flag = (int*)(psm + 256);

    const int tid = threadIdx.x, wid = tid >> 5, lane = tid & 31;
    const int g = lane >> 2, t = lane & 3;
    const int nt = blockIdx.x;                  // 0..63
    const bool isp = (nt >= 32);
    const int n0 = (nt & 31) * 64;
    const int m0 = blockIdx.y * 64;
    const float* Bmat = isp ? proxies : Wm;
    const int wm = (wid & 1) * 32, wn = (wid >> 1) * 16, wc = wid >> 1;  // wc 0..3

    // loader mapping: 8 warps (A: 0-3, B: 4-7), 16 rows each; contiguous LDG
    const int sub = lane >> 3, u = lane & 7;
    const bool ldA = wid < 4;
    const int rbase = (ldA ? wid * 16 : (wid - 4) * 16) + sub;    // + 4i later
    const float4* rp4 = (const float4*)(ldA ? (g_featT + (size_t)(m0 + rbase) * D_)
                                            : (Bmat + (size_t)(n0 + rbase) * D_));
    const int wbase = (ldA ? 0 : TAW) + rbase * RS_W + u * 4;

    float acc[2][2][4] = {};
    float4 v[4];
    float sq[4] = {0.f, 0.f, 0.f, 0.f};         // per i-row sumsq

    auto ld = [&](int c) {
#pragma unroll
        for (int i = 0; i < 4; i++)
            v[i] = rp4[(size_t)i * (D_ / 4) * 4 + c * 8 + u];
    };
    auto st = [&](int c) {
        float* base = smem + (c & 1) * STG + wbase;
#pragma unroll
        for (int i = 0; i < 4; i++) {
            float4 a = v[i];
            sq[i] += a.x * a.x + a.y * a.y + a.z * a.z + a.w * a.w;
            if (ldA)     // featT already tf32-rounded
                *(float4*)(base + i * 4 * RS_W) = a;
            else
                *(float4*)(base + i * 4 * RS_W) =
                    make_float4(to_tf32(a.x), to_tf32(a.y),
                                to_tf32(a.z), to_tf32(a.w));
        }
    };

    ld(0); st(0); __syncthreads();
    constexpr int NCH = D_ / 32;                // 16
    for (int c = 0; c < NCH; c++) {
        if (c + 1 < NCH) ld(c + 1);
        const float* stg = smem + (c & 1) * STG;
        chunk_mma<2, 2>(stg, stg + TAW, wm, wn, g, t, acc);
        if (c + 1 < NCH) { st(c + 1); __syncthreads(); }
    }

    // per-row sumsq: reduce over the 8 u-lanes
#pragma unroll
    for (int i = 0; i < 4; i++) {
        float s = sq[i];
        s += __shfl_xor_sync(0xffffffffu, s, 1);
        s += __shfl_xor_sync(0xffffffffu, s, 2);
        s += __shfl_xor_sync(0xffffffffu, s, 4);
        if (u == 0) {
            int row = rbase + 4 * i;
            if (ldA) fn2s[row] = s;
            else     pn2s[row] = s;
        }
    }
    __syncthreads();

    if (!isp) {
#pragma unroll
        for (int i = 0; i < 2; i++) {
            int m = m0 + wm + i * 16 + g;
#pragma unroll
            for (int nn = 0; nn < 2; nn++) {
                int n = n0 + wn + nn * 8 + 2 * t;
                float bn0 = bm[n], bn1 = bm[n + 1];
                *(float2*)(out + (size_t)m * P_ + n) =
                    make_float2(acc[i][nn][0] + bn0, acc[i][nn][1] + bn1);
                *(float2*)(out + (size_t)(m + 8) * P_ + n) =
                    make_float2(acc[i][nn][2] + bn0, acc[i][nn][3] + bn1);
            }
        }
        return;
    }

    // export fn2 for reg_e (4 CTAs with nt==32 cover all 256 rows)
    if (nt == 32 && tid < 64) g_feat_n2[m0 + tid] = fn2s[tid];

    // proxy: s = 2*dot - fn2 - pn2 in regs -> per-(row, warp) (max, sumexp)
#pragma unroll
    for (int i = 0; i < 2; i++) {
        const int rA = wm + i * 16 + g;
        const int rB = rA + 8;
        const float fa = fn2s[rA], fb = fn2s[rB];
        const int ya = y[m0 + rA], yb = y[m0 + rB];
        float sA[4], sB[4];
#pragma unroll
        for (int nn = 0; nn < 2; nn++) {
            int nl = wn + nn * 8 + 2 * t;
            float p0 = pn2s[nl], p1 = pn2s[nl + 1];
            sA[nn * 2 + 0] = 2.f * acc[i][nn][0] - fa - p0;
            sA[nn * 2 + 1] = 2.f * acc[i][nn][1] - fa - p1;
            sB[nn * 2 + 0] = 2.f * acc[i][nn][2] - fb - p0;
            sB[nn * 2 + 1] = 2.f * acc[i][nn][3] - fb - p1;
            int n = n0 + nl;
            if (n     == ya) g_sy[m0 + rA] = sA[nn * 2 + 0];
            if (n + 1 == ya) g_sy[m0 + rA] = sA[nn * 2 + 1];
            if (n     == yb) g_sy[m0 + rB] = sB[nn * 2 + 0];
            if (n + 1 == yb) g_sy[m0 + rB] = sB[nn * 2 + 1];
        }
        float mA = fmaxf(fmaxf(sA[0], sA[1]), fmaxf(sA[2], sA[3]));
        float mB = fmaxf(fmaxf(sB[0], sB[1]), fmaxf(sB[2], sB[3]));
        float eA = expf(sA[0] - mA) + expf(sA[1] - mA)
                 + expf(sA[2] - mA) + expf(sA[3] - mA);
        float eB = expf(sB[0] - mB) + expf(sB[1] - mB)
                 + expf(sB[2] - mB) + expf(sB[3] - mB);
#pragma unroll
        for (int o = 1; o <= 2; o <<= 1) {
            float mA2 = __shfl_xor_sync(0xffffffffu, mA, o);
            float eA2 = __shfl_xor_sync(0xffffffffu, eA, o);
            float mB2 = __shfl_xor_sync(0xffffffffu, mB, o);
            float eB2 = __shfl_xor_sync(0xffffffffu, eB, o);
            float M = fmaxf(mA, mA2);
            eA = eA * expf(mA - M) + eA2 * expf(mA2 - M); mA = M;
            M = fmaxf(mB, mB2);
            eB = eB * expf(mB - M) + eB2 * expf(mB2 - M); mB = M;
        }
        if (t == 0) {
            pmx[rA * 4 + wc] = mA; psm[rA * 4 + wc] = eA;
            pmx[rB * 4 + wc] = mB; psm[rB * 4 + wc] = eB;
        }
    }
    __syncthreads();
    if (tid < 64) {
        float4 m4 = *(const float4*)(pmx + tid * 4);
        float4 s4 = *(const float4*)(psm + tid * 4);
        float M = fmaxf(fmaxf(m4.x, m4.y), fmaxf(m4.z, m4.w));
        float S = s4.x * expf(m4.x - M) + s4.y * expf(m4.y - M)
                + s4.z * expf(m4.z - M) + s4.w * expf(m4.w - M);
        int idx = (m0 + tid) * NT_P + (nt - 32);
        g_pmax[idx] = M;
        g_psum[idx] = S;
    }

    // ---- last-done proxy CTA finalizes loss + reg_e ------------------------
    __threadfence();
    __syncthreads();
    if (tid == 0) *flag = (atomicAdd(&g_done, 1) == 127) ? 1 : 0;
    __syncthreads();
    if (*flag == 0) return;
    __threadfence();

    float* r1 = pmx;                            // reuse smem [256]
    float* r2 = pmx + 256;                      // = psm region [256]
    {
        const int b = tid;                      // one row per thread
        const float4* pm = (const float4*)(g_pmax + b * NT_P);
        const float4* ps = (const float4*)(g_psum + b * NT_P);
        float4 mv[8], sv[8];
#pragma unroll
        for (int q = 0; q < 8; q++) { mv[q] = pm[q]; sv[q] = ps[q]; }
        float M = -INFINITY;
#pragma unroll
        for (int q = 0; q < 8; q++)
            M = fmaxf(M, fmaxf(fmaxf(mv[q].x, mv[q].y), fmaxf(mv[q].z, mv[q].w)));
        float S = 0.f;
#pragma unroll
        for (int q = 0; q < 8; q++)
            S += sv[q].x * expf(mv[q].x - M) + sv[q].y * expf(mv[q].y - M)
               + sv[q].z * expf(mv[q].z - M) + sv[q].w * expf(mv[q].w - M);
        r1[b] = g_sy[b] - M - logf(S);          // logp[b, y[b]]
        r2[b] = sqrtf(g_feat_n2[b]);
    }
    __syncthreads();
    for (int stp = 128; stp > 0; stp >>= 1) {
        if (tid < stp) { r1[tid] += r1[tid + stp]; r2[tid] += r2[tid + stp]; }
        __syncthreads();
    }
    if (tid == 0) {
        out[(size_t)B_ * P_]     = -r1[0] / (float)B_;  // loss
        out[(size_t)B_ * P_ + 1] =  r2[0] / (float)B_;  // reg_e
        g_done = 0;                              // reset for graph replay
    }
}

// ---------------- launch ----------------------------------------------------
extern "C" void kernel_launch(void* const* d_in, const int* in_sizes, int n_in,
                              void* d_out, int out_size)
{
    const float* x       = (const float*)d_in[0];
    const int*   y       = (const int*)  d_in[1];
    const float* Wb      = (const float*)d_in[2];
    const float* bb      = (const float*)d_in[3];
    const float* Wm      = (const float*)d_in[4];
    const float* bm      = (const float*)d_in[5];
    const float* proxies = (const float*)d_in[6];
    float* out = (float*)d_out;

    const int SMEM1 = (4 * 64 * RS_W + 4) * 4;                       // ~36.9 KB
    const int SMEM2 = (4 * 64 * RS_W + 64 + 64 + 256 + 256 + 4) * 4; // ~39.4 KB
    cudaFuncSetAttribute(gemm1_mma,  cudaFuncAttributeMaxDynamicSharedMemorySize, SMEM1);
    cudaFuncSetAttribute(gemm23_mma, cudaFuncAttributeMaxDynamicSharedMemorySize, SMEM2);

    // 1) feat: split-K(8) GEMM + fused last-slice combine
    //    (256 CTAs, 256 thr, 2 CTAs/SM)
    gemm1_mma<<<dim3(D_ / 64, B_ / 64, SPLITK), 256, SMEM1>>>(x, Wb, bb);
    // 2) fused out-head + proxy softmax partials + last-CTA finalize
    //    (256 CTAs, 256 thr, 2 CTAs/SM)
    gemm23_mma<<<dim3(64, B_ / 64), 256, SMEM2>>>(Wm, bm, proxies, y, out);
}